// round 13
// baseline (speedup 1.0000x reference)
#include <cuda_runtime.h>
#include <cuda_bf16.h>
#include <cuda_fp16.h>
#include <cstdint>

#define DIM 1024
#define NHEADS 16
#define HD 64
#define BATCH 2
#define SEQ 2048
#define ROWS (BATCH*SEQ)   // 4096
#define KP2 2048           // f16 split A: [hi | lo]

// Q pre-scale: 1/sqrt(64) * log2(e)  (softmax done in base-2 domain)
#define QSCALE 0.1803368801111204f

// ---------------- scratch (device globals; no allocation allowed) ----------
__device__ __align__(16) __half g_qhi[ROWS * DIM];
__device__ __align__(16) __half g_qlo[ROWS * DIM];
__device__ __align__(16) __half g_kh [ROWS * DIM];
__device__ __align__(16) __half g_vh [ROWS * DIM];
__device__ __align__(16) __half g_apack[ROWS * KP2];      // [Ah | Al]
__device__ __align__(16) __half g_bpack[4][DIM * DIM];    // W^T f16, 4 planes

// ===========================================================================
// PTX helpers
// ===========================================================================
__device__ __forceinline__ uint32_t smem_u32(const void* p) {
    uint32_t a;
    asm("{ .reg .u64 t; cvta.to.shared.u64 t, %1; cvt.u32.u64 %0, t; }"
        : "=r"(a) : "l"(p));
    return a;
}

#define CP_ASYNC16(dst, src) \
    asm volatile("cp.async.cg.shared.global [%0], [%1], 16;" \
                 :: "r"(dst), "l"(src) : "memory")
#define CP_COMMIT() asm volatile("cp.async.commit_group;" ::: "memory")
#define CP_WAIT1()  asm volatile("cp.async.wait_group 1;"  ::: "memory")
#define CP_WAIT3()  asm volatile("cp.async.wait_group 3;"  ::: "memory")

#define LDSM_X4(r, addr) \
    asm volatile("ldmatrix.sync.aligned.m8n8.x4.shared.b16 {%0,%1,%2,%3}, [%4];" \
        : "=r"((r)[0]), "=r"((r)[1]), "=r"((r)[2]), "=r"((r)[3]) : "r"(addr))

#define LDSM_X4_T(r, addr) \
    asm volatile("ldmatrix.sync.aligned.m8n8.x4.trans.shared.b16 {%0,%1,%2,%3}, [%4];" \
        : "=r"((r)[0]), "=r"((r)[1]), "=r"((r)[2]), "=r"((r)[3]) : "r"(addr))

#define MMA16816H(d, a, b0, b1) \
    asm volatile("mma.sync.aligned.m16n8k16.row.col.f32.f16.f16.f32 " \
        "{%0,%1,%2,%3}, {%4,%5,%6,%7}, {%8,%9}, {%0,%1,%2,%3};" \
        : "+f"((d)[0]), "+f"((d)[1]), "+f"((d)[2]), "+f"((d)[3]) \
        : "r"((a)[0]), "r"((a)[1]), "r"((a)[2]), "r"((a)[3]), "r"(b0), "r"(b1))

#define EX2F(d, x) asm("ex2.approx.ftz.f32 %0, %1;" : "=f"(d) : "f"(x))
// two f16 ex2 in one MUFU op
#define EX2H2(d, x) asm("ex2.approx.f16x2 %0, %1;" : "=r"(d) : "r"(x))
// pack {hi,lo} f32 -> f16x2 (first source -> upper half)
#define PACK_F16X2(d, hi, lo) \
    asm("cvt.rn.f16x2.f32 %0, %1, %2;" : "=r"(d) : "f"(hi), "f"(lo))

// ===========================================================================
// conversion kernels
// ===========================================================================
// A (fp32 [4096,1024]) -> A' f16 [4096, 2048] = [hi | lo]
__global__ __launch_bounds__(256) void conv_a(
    const float* __restrict__ A, __half* __restrict__ P)
{
    const int row = blockIdx.x;
    const int c4  = threadIdx.x * 4;
    float4 v = *(const float4*)(A + (size_t)row * DIM + c4);
    float xs[4] = {v.x, v.y, v.z, v.w};
    __align__(8) __half h[4], L[4];
    #pragma unroll
    for (int j = 0; j < 4; j++) {
        __half hh = __float2half(xs[j]);
        h[j] = hh;
        L[j] = __float2half(xs[j] - __half2float(hh));
    }
    __half* rp = P + (size_t)row * KP2;
    *(uint2*)(rp + c4)       = *(const uint2*)h;
    *(uint2*)(rp + DIM + c4) = *(const uint2*)L;
}

// 4 weights fused: W (fp32 [K,N]) -> B f16 [N][K] transposed, plane z
__global__ __launch_bounds__(256) void conv_w(
    const float* __restrict__ W0, const float* __restrict__ W1,
    const float* __restrict__ W2, const float* __restrict__ W3,
    __half* __restrict__ P)
{
    __shared__ float ws[32][33];
    const int k0 = blockIdx.x * 32;
    const int n0 = blockIdx.y * 32;
    const int z  = blockIdx.z;
    const float* W = (z == 0) ? W0 : (z == 1) ? W1 : (z == 2) ? W2 : W3;
    const int t  = threadIdx.x;

    {
        const int kr = t >> 3;
        const int c4 = (t & 7) * 4;
        float4 v = *(const float4*)(W + (size_t)(k0 + kr) * DIM + n0 + c4);
        ws[kr][c4 + 0] = v.x; ws[kr][c4 + 1] = v.y;
        ws[kr][c4 + 2] = v.z; ws[kr][c4 + 3] = v.w;
    }
    __syncthreads();

    const int nr = t >> 3;
    const int k4 = (t & 7) * 4;
    __align__(8) __half h[4];
    #pragma unroll
    for (int j = 0; j < 4; j++)
        h[j] = __float2half(ws[k4 + j][nr]);
    *(uint2*)(P + (size_t)z * DIM * DIM + (size_t)(n0 + nr) * DIM + k0 + k4)
        = *(const uint2*)h;
}

// ===========================================================================
// f16 GEMM: C = A @ W + bias.
// USE_LO=true : 2-product (A exact via hi+lo), 3-stage  — Q/K projections.
// USE_LO=false: 1-product (A hi only), 5-stage deep pipe — V proj, out-proj.
// CTA 128x128, 8 warps (4m x 2n), K=1024 in 32 chunks of 32.
// mode = mode0 + blockIdx.z: 0 fp32 out; 1 Q f16 (hi,lo) scaled; 2 K; 3 V.
// ===========================================================================
#define NCHUNK 32
#define SROW 80
#define TILE_SB (128 * SROW)           // 10240
#define GEMM_SMEM_LO (3 * 3 * TILE_SB)   // 92160  (3 stages x 3 tiles)
#define GEMM_SMEM_HI (5 * 2 * TILE_SB)   // 102400 (5 stages x 2 tiles)

template <bool USE_LO>
__global__ __launch_bounds__(256, 2) void gemm_mma(
    const __half* __restrict__ Ap, const __half* __restrict__ Bp,
    const float* __restrict__ bs0, const float* __restrict__ bs1,
    const float* __restrict__ bs2, float* __restrict__ C,
    __half* __restrict__ Qh, __half* __restrict__ Ql,
    __half* __restrict__ Kh, __half* __restrict__ Vh, int mode0)
{
    extern __shared__ __align__(128) char smem[];
    const uint32_t sb = smem_u32(smem);
    constexpr int NTILES  = USE_LO ? 3 : 2;
    constexpr int NSTG    = USE_LO ? 3 : 5;
    constexpr int STAGE_B = NTILES * TILE_SB;

    const int tid  = threadIdx.x;
    const int lane = tid & 31;
    const int wid  = tid >> 5;
    const int wm   = (wid >> 1) * 32;
    const int wn   = (wid & 1) * 64;
    const int nt   = blockIdx.x;
    const int mt   = blockIdx.y;
    const int z    = blockIdx.z;
    const int mode = mode0 + z;
    const float* bias = (mode <= 1) ? bs0 : (mode == 2) ? bs1 : bs2;

    const __half* ag = Ap + (size_t)(mt * 128) * KP2;
    const __half* bg = Bp + (size_t)z * DIM * DIM + (size_t)(nt * 128) * DIM;

    // per stage: NTILES tiles x 512 x 16B chunks. Tile order: [Ahi, (Alo), B].
    auto issue = [&](int kc, int slot) {
        const uint32_t st = sb + slot * STAGE_B;
        #pragma unroll
        for (int u = 0; u < 2 * NTILES; u++) {
            const int id = tid + u * 256;
            const int t3 = id >> 9;            // tile index
            const int r  = (id >> 2) & 127;
            const int c  = id & 3;
            const uint32_t dst = st + t3 * TILE_SB + r * SROW + c * 16;
            const __half* src = (t3 == NTILES - 1)
                ? bg + (size_t)r * DIM + kc * 32 + c * 8
                : ag + (size_t)r * KP2 + t3 * DIM + kc * 32 + c * 8;
            CP_ASYNC16(dst, src);
        }
        CP_COMMIT();
    };

    float acc[2][8][4];
    #pragma unroll
    for (int mi = 0; mi < 2; mi++)
        #pragma unroll
        for (int nj = 0; nj < 8; nj++)
            #pragma unroll
            for (int r = 0; r < 4; r++) acc[mi][nj][r] = 0.f;

    const uint32_t a_row = wm + (lane & 15);
    const uint32_t a_cc  = (lane >> 4) * 16;
    const uint32_t b_row = wn + ((lane >> 4) << 3) + (lane & 7);
    const uint32_t b_cc  = ((lane >> 3) & 1) * 16;

    #pragma unroll
    for (int s = 0; s < NSTG - 1; s++) issue(s, s);

    for (int kc = 0; kc < NCHUNK; kc++) {
        const int slot = kc % NSTG;
        if (USE_LO) CP_WAIT1(); else CP_WAIT3();
        __syncthreads();
        if (kc + NSTG - 1 < NCHUNK) issue(kc + NSTG - 1, (kc + NSTG - 1) % NSTG);
        else CP_COMMIT();

        const uint32_t Ah = sb + slot * STAGE_B;
        const uint32_t Al = Ah + TILE_SB;
        const uint32_t Bs = Ah + (NTILES - 1) * TILE_SB;

        #pragma unroll
        for (int ki = 0; ki < 2; ki++) {
            uint32_t ah[2][4], al[2][4], b[4][4];
            #pragma unroll
            for (int mi = 0; mi < 2; mi++) {
                LDSM_X4(ah[mi], Ah + (a_row + mi * 16) * SROW + ki * 32 + a_cc);
                if (USE_LO)
                    LDSM_X4(al[mi], Al + (a_row + mi * 16) * SROW + ki * 32 + a_cc);
            }
            #pragma unroll
            for (int ni = 0; ni < 4; ni++)
                LDSM_X4(b[ni], Bs + (b_row + ni * 16) * SROW + ki * 32 + b_cc);
            #pragma unroll
            for (int mi = 0; mi < 2; mi++)
                #pragma unroll
                for (int nj = 0; nj < 8; nj++) {
                    const uint32_t b0 = b[nj >> 1][(nj & 1) * 2];
                    const uint32_t b1 = b[nj >> 1][(nj & 1) * 2 + 1];
                    MMA16816H(acc[mi][nj], ah[mi], b0, b1);
                    if (USE_LO)
                        MMA16816H(acc[mi][nj], al[mi], b0, b1);
                }
        }
    }

    const int g   = lane >> 2;
    const int tig = lane & 3;
    #pragma unroll
    for (int nj = 0; nj < 8; nj++) {
        const int col = nt * 128 + wn + nj * 8 + tig * 2;
        const float2 bv = *(const float2*)(bias + col);
        #pragma unroll
        for (int mi = 0; mi < 2; mi++) {
            const int m0 = mt * 128 + wm + mi * 16 + g;
            float2 d0 = {acc[mi][nj][0] + bv.x, acc[mi][nj][1] + bv.y};
            float2 d1 = {acc[mi][nj][2] + bv.x, acc[mi][nj][3] + bv.y};
            const size_t i0 = (size_t)m0 * DIM + col;
            const size_t i1 = (size_t)(m0 + 8) * DIM + col;
            if (mode == 0) {
                *(float2*)(C + i0) = d0;
                *(float2*)(C + i1) = d1;
            } else if (mode == 2) {
                *(__half2*)(Kh + i0) = __floats2half2_rn(d0.x, d0.y);
                *(__half2*)(Kh + i1) = __floats2half2_rn(d1.x, d1.y);
            } else if (mode == 3) {
                *(__half2*)(Vh + i0) = __floats2half2_rn(d0.x, d0.y);
                *(__half2*)(Vh + i1) = __floats2half2_rn(d1.x, d1.y);
            } else {
                d0.x *= QSCALE; d0.y *= QSCALE;
                d1.x *= QSCALE; d1.y *= QSCALE;
                __half2 h0 = __floats2half2_rn(d0.x, d0.y);
                __half2 h1 = __floats2half2_rn(d1.x, d1.y);
                *(__half2*)(Qh + i0) = h0;
                *(__half2*)(Qh + i1) = h1;
                *(__half2*)(Ql + i0) = __floats2half2_rn(
                    d0.x - __half2float(__low2half(h0)),
                    d0.y - __half2float(__high2half(h0)));
                *(__half2*)(Ql + i1) = __floats2half2_rn(
                    d1.x - __half2float(__low2half(h1)),
                    d1.y - __half2float(__high2half(h1)));
            }
        }
    }
}

// ===========================================================================
// HMMA flash attention. S = [Qhi|Qlo] . Kh  (2 f16 products); base-2 softmax;
// P via ex2.approx.f16x2 (half the MUFU ops of scalar f32 ex2);
// O += P V; row-sums via ones-column MMA. 2-stage cp.async pipeline.
// Epilogue: o/l as f16 written to A-pack hi plane (out-proj is 1-product).
// ===========================================================================
#define ASROW 144
#define SMTILE (64 * ASROW)          // 9216
#define SMS0   (2 * SMTILE)          // Q hi/lo
#define SMSTAGE (2 * SMTILE)         // Kh, V
#define ATTN_SMEM (SMS0 + 2 * SMSTAGE)   // 55296
#define ONE2 0x3C003C00u

__global__ __launch_bounds__(128, 4) void attn_mma(
    const __half* __restrict__ Qhi, const __half* __restrict__ Qlo,
    const __half* __restrict__ Khp, const __half* __restrict__ Vhp,
    __half* __restrict__ Apack)
{
    extern __shared__ __align__(128) char smem[];
    const uint32_t sb = smem_u32(smem);
    const int tid = threadIdx.x, lane = tid & 31, w = tid >> 5;
    const int qt = blockIdx.x, h = blockIdx.y, b = blockIdx.z;
    const size_t hbase = (size_t)b * SEQ * DIM + (size_t)h * HD;

    // ---- Q hi/lo tiles (group with stage 0) ----
    #pragma unroll
    for (int u = 0; u < 8; u++) {
        const int id = tid + u * 128;
        const int t2 = id >> 9;
        const int r  = (id >> 3) & 63;
        const int c  = id & 7;
        const uint32_t dst = sb + t2 * SMTILE + r * ASROW + c * 16;
        const __half* src =
            (t2 ? Qlo : Qhi) + hbase + (size_t)(qt * 64 + r) * DIM + c * 8;
        CP_ASYNC16(dst, src);
    }
    auto issue_kv = [&](int st, int buf) {
        #pragma unroll
        for (int u = 0; u < 8; u++) {
            const int id = tid + u * 128;
            const int t2 = id >> 9;       // 0 Kh, 1 V
            const int r  = (id >> 3) & 63;
            const int c  = id & 7;
            const uint32_t dst = sb + SMS0 + buf * SMSTAGE + t2 * SMTILE
                               + r * ASROW + c * 16;
            const size_t off = hbase + (size_t)(st * 64 + r) * DIM + c * 8;
            const __half* src = t2 ? (Vhp + off) : (Khp + off);
            CP_ASYNC16(dst, src);
        }
    };
    issue_kv(0, 0); CP_COMMIT();
    issue_kv(1, 1); CP_COMMIT();
    CP_WAIT1();
    __syncthreads();

    // ---- lane-invariant addresses ----
    const uint32_t a_row = w * 16 + (lane & 15);
    const uint32_t a_cc  = (lane >> 4) * 16;
    const uint32_t qbase = sb + a_row * ASROW + a_cc;

    const uint32_t b_row = ((lane >> 4) << 3) + (lane & 7);
    const uint32_t b_cc  = ((lane >> 3) & 1) * 16;
    const uint32_t v_row = (((lane >> 3) & 1) << 3) + (lane & 7);
    const uint32_t v_cc  = (lane >> 4) * 16;

    float m0 = -1e30f, m1 = -1e30f;
    float Of[8][4], Lf[4] = {0.f, 0.f, 0.f, 0.f};
    #pragma unroll
    for (int nt = 0; nt < 8; nt++)
        #pragma unroll
        for (int r = 0; r < 4; r++) Of[nt][r] = 0.f;

    for (int st = 0; st < SEQ / 64; st++) {
        const uint32_t kb = sb + SMS0 + (st & 1) * SMSTAGE;

        // ---- S = Q K^T (2 f16 products; Q frags reloaded per k-chunk) ----
        float S[8][4];
        #pragma unroll
        for (int nt = 0; nt < 8; nt++)
            #pragma unroll
            for (int r = 0; r < 4; r++) S[nt][r] = 0.f;

        #pragma unroll
        for (int kc = 0; kc < 4; kc++) {
            uint32_t qhf[4], qlf[4];
            LDSM_X4(qhf, qbase + kc * 32);
            LDSM_X4(qlf, qbase + SMTILE + kc * 32);
            #pragma unroll
            for (int ng = 0; ng < 4; ng++) {
                uint32_t bh[4];
                LDSM_X4(bh, kb + (ng * 16 + b_row) * ASROW + kc * 32 + b_cc);
                MMA16816H(S[2 * ng],     qhf, bh[0], bh[1]);
                MMA16816H(S[2 * ng],     qlf, bh[0], bh[1]);
                MMA16816H(S[2 * ng + 1], qhf, bh[2], bh[3]);
                MMA16816H(S[2 * ng + 1], qlf, bh[2], bh[3]);
            }
        }

        // ---- online softmax (base 2) ----
        float mloc0 = -1e30f, mloc1 = -1e30f;
        #pragma unroll
        for (int nt = 0; nt < 8; nt++) {
            mloc0 = fmaxf(mloc0, fmaxf(S[nt][0], S[nt][1]));
            mloc1 = fmaxf(mloc1, fmaxf(S[nt][2], S[nt][3]));
        }
        mloc0 = fmaxf(mloc0, __shfl_xor_sync(0xffffffffu, mloc0, 1));
        mloc0 = fmaxf(mloc0, __shfl_xor_sync(0xffffffffu, mloc0, 2));
        mloc1 = fmaxf(mloc1, __shfl_xor_sync(0xffffffffu, mloc1, 1));
        mloc1 = fmaxf(mloc1, __shfl_xor_sync(0xffffffffu, mloc1, 2));
        const float mn0 = fmaxf(m0, mloc0), mn1 = fmaxf(m1, mloc1);
        float c0, c1;
        EX2F(c0, m0 - mn0); EX2F(c1, m1 - mn1);
        m0 = mn0; m1 = mn1;
        #pragma unroll
        for (int nt = 0; nt < 8; nt++) {
            Of[nt][0] *= c0; Of[nt][1] *= c0;
            Of[nt][2] *= c1; Of[nt][3] *= c1;
        }
        Lf[0] *= c0; Lf[1] *= c0; Lf[2] *= c1; Lf[3] *= c1;

        // P = 2^(S-m) computed pairwise in f16 (ex2.approx.f16x2)
        uint32_t pa[4][4];
        #pragma unroll
        for (int nt = 0; nt < 8; nt++) {
            uint32_t g0, g8;
            PACK_F16X2(g0, S[nt][1] - mn0, S[nt][0] - mn0);
            PACK_F16X2(g8, S[nt][3] - mn1, S[nt][2] - mn1);
            EX2H2(g0, g0);
            EX2H2(g8, g8);
            pa[nt >> 1][(nt & 1) * 2 + 0] = g0;
            pa[nt >> 1][(nt & 1) * 2 + 1] = g8;
        }

        // ---- O += P V ; l += P.1 ----
        #pragma unroll
        for (int kc = 0; kc < 4; kc++) {
            MMA16816H(Lf, pa[kc], ONE2, ONE2);
            #pragma unroll
            for (int hg = 0; hg < 4; hg++) {
                uint32_t bv[4];
                LDSM_X4_T(bv, kb + SMTILE + (kc * 16 + v_row) * ASROW
                              + hg * 32 + v_cc);
                MMA16816H(Of[2 * hg],     pa[kc], bv[0], bv[1]);
                MMA16816H(Of[2 * hg + 1], pa[kc], bv[2], bv[3]);
            }
        }

        __syncthreads();
        if (st + 2 < SEQ / 64) issue_kv(st + 2, st & 1);
        CP_COMMIT();
        CP_WAIT1();
        __syncthreads();
    }

    // ---- finalize: o/l as f16 into A-pack hi plane (1-product out-proj) ----
    const float i0 = 1.f / Lf[0], i1 = 1.f / Lf[2];
    const int g = lane >> 2, tg = lane & 3;
    const size_t r0 = (size_t)b * SEQ + (size_t)qt * 64 + w * 16 + g;
    __half* rp0 = Apack + r0 * KP2;
    __half* rp1 = Apack + (r0 + 8) * KP2;
    #pragma unroll
    for (int nt = 0; nt < 8; nt++) {
        const int col = h * 64 + nt * 8 + tg * 2;
        *(__half2*)(rp0 + col) = __floats2half2_rn(Of[nt][0] * i0, Of[nt][1] * i0);
        *(__half2*)(rp1 + col) = __floats2half2_rn(Of[nt][2] * i1, Of[nt][3] * i1);
    }
}

// ===========================================================================
// launch
// ===========================================================================
extern "C" void kernel_launch(void* const* d_in, const int* in_sizes, int n_in,
                              void* d_out, int out_size)
{
    const float* x  = (const float*)d_in[0];
    const float* Wq = (const float*)d_in[1];
    const float* bq = (const float*)d_in[2];
    const float* Wk = (const float*)d_in[3];
    const float* bk = (const float*)d_in[4];
    const float* Wv = (const float*)d_in[5];
    const float* bv = (const float*)d_in[6];
    const float* Wo = (const float*)d_in[7];
    const float* bo = (const float*)d_in[8];
    float* out = (float*)d_out;

    __half *ap, *bp, *qhi, *qlo, *kh, *vh;
    cudaGetSymbolAddress((void**)&ap,  g_apack);
    cudaGetSymbolAddress((void**)&bp,  g_bpack);
    cudaGetSymbolAddress((void**)&qhi, g_qhi);
    cudaGetSymbolAddress((void**)&qlo, g_qlo);
    cudaGetSymbolAddress((void**)&kh,  g_kh);
    cudaGetSymbolAddress((void**)&vh,  g_vh);

    cudaFuncSetAttribute(gemm_mma<true>,
                         cudaFuncAttributeMaxDynamicSharedMemorySize, GEMM_SMEM_LO);
    cudaFuncSetAttribute(gemm_mma<false>,
                         cudaFuncAttributeMaxDynamicSharedMemorySize, GEMM_SMEM_HI);
    cudaFuncSetAttribute(attn_mma,
                         cudaFuncAttributeMaxDynamicSharedMemorySize, ATTN_SMEM);

    // fused weight conversion (4 planes)
    conv_w<<<dim3(32, 32, 4), 256>>>(Wq, Wk, Wv, Wo, bp);

    // x -> f16 hi/lo
    conv_a<<<ROWS, 256>>>(x, ap);

    // Q/K projections: 2-product (z selects plane / bias / epilogue mode 1,2)
    gemm_mma<true><<<dim3(8, 32, 2), 256, GEMM_SMEM_LO>>>(
        ap, bp, bq, bk, nullptr, nullptr, qhi, qlo, kh, nullptr, 1);

    // V projection: 1-product (mode 3)
    gemm_mma<false><<<dim3(8, 32, 1), 256, GEMM_SMEM_HI>>>(
        ap, bp + 2 * (size_t)DIM * DIM, bv, bv, bv,
        nullptr, nullptr, nullptr, nullptr, vh, 3);

    // HMMA flash attention; epilogue writes f16 ctx into A-pack hi plane
    attn_mma<<<dim3(SEQ / 64, NHEADS, BATCH), 128, ATTN_SMEM>>>(
        qhi, qlo, kh, vh, ap);

    // output projection: 1-product (mode 0, fp32 out)
    gemm_mma<false><<<dim3(8, 32, 1), 256, GEMM_SMEM_HI>>>(
        ap, bp + 3 * (size_t)DIM * DIM, bo, bo, bo,
        out, nullptr, nullptr, nullptr, nullptr, 0);
}

// round 15
// speedup vs baseline: 1.0228x; 1.0228x over previous
#include <cuda_runtime.h>
#include <cuda_bf16.h>
#include <cuda_fp16.h>
#include <cstdint>

#define DIM 1024
#define NHEADS 16
#define HD 64
#define BATCH 2
#define SEQ 2048
#define ROWS (BATCH*SEQ)   // 4096
#define KP2 2048           // f16 split A: [hi | lo]

// Q pre-scale: 1/sqrt(64) * log2(e)  (softmax done in base-2 domain)
#define QSCALE 0.1803368801111204f

// ---------------- scratch (device globals; no allocation allowed) ----------
__device__ __align__(16) __half g_qhi[ROWS * DIM];
__device__ __align__(16) __half g_qlo[ROWS * DIM];
__device__ __align__(16) __half g_kh [ROWS * DIM];
__device__ __align__(16) __half g_vh [ROWS * DIM];
__device__ __align__(16) __half g_apack[ROWS * KP2];      // [Ah | Al]
__device__ __align__(16) __half g_bpack[4][DIM * DIM];    // W^T f16, 4 planes

// ===========================================================================
// PTX helpers
// ===========================================================================
__device__ __forceinline__ uint32_t smem_u32(const void* p) {
    uint32_t a;
    asm("{ .reg .u64 t; cvta.to.shared.u64 t, %1; cvt.u32.u64 %0, t; }"
        : "=r"(a) : "l"(p));
    return a;
}

#define CP_ASYNC16(dst, src) \
    asm volatile("cp.async.cg.shared.global [%0], [%1], 16;" \
                 :: "r"(dst), "l"(src) : "memory")
#define CP_COMMIT() asm volatile("cp.async.commit_group;" ::: "memory")
#define CP_WAIT1()  asm volatile("cp.async.wait_group 1;"  ::: "memory")

#define LDSM_X4(r, addr) \
    asm volatile("ldmatrix.sync.aligned.m8n8.x4.shared.b16 {%0,%1,%2,%3}, [%4];" \
        : "=r"((r)[0]), "=r"((r)[1]), "=r"((r)[2]), "=r"((r)[3]) : "r"(addr))

#define LDSM_X4_T(r, addr) \
    asm volatile("ldmatrix.sync.aligned.m8n8.x4.trans.shared.b16 {%0,%1,%2,%3}, [%4];" \
        : "=r"((r)[0]), "=r"((r)[1]), "=r"((r)[2]), "=r"((r)[3]) : "r"(addr))

#define MMA16816H(d, a, b0, b1) \
    asm volatile("mma.sync.aligned.m16n8k16.row.col.f32.f16.f16.f32 " \
        "{%0,%1,%2,%3}, {%4,%5,%6,%7}, {%8,%9}, {%0,%1,%2,%3};" \
        : "+f"((d)[0]), "+f"((d)[1]), "+f"((d)[2]), "+f"((d)[3]) \
        : "r"((a)[0]), "r"((a)[1]), "r"((a)[2]), "r"((a)[3]), "r"(b0), "r"(b1))

#define EX2F(d, x) asm("ex2.approx.ftz.f32 %0, %1;" : "=f"(d) : "f"(x))
// pack {hi,lo} f32 -> f16x2 (first source -> upper half)
#define PACK_F16X2(d, hi, lo) \
    asm("cvt.rn.f16x2.f32 %0, %1, %2;" : "=r"(d) : "f"(hi), "f"(lo))

// ===========================================================================
// conversion kernels
// ===========================================================================
// A (fp32 [4096,1024]) -> A' f16 [4096, 2048] = [hi | lo]
__global__ __launch_bounds__(256) void conv_a(
    const float* __restrict__ A, __half* __restrict__ P)
{
    const int row = blockIdx.x;
    const int c4  = threadIdx.x * 4;
    float4 v = *(const float4*)(A + (size_t)row * DIM + c4);
    float xs[4] = {v.x, v.y, v.z, v.w};
    __align__(8) __half h[4], L[4];
    #pragma unroll
    for (int j = 0; j < 4; j++) {
        __half hh = __float2half(xs[j]);
        h[j] = hh;
        L[j] = __float2half(xs[j] - __half2float(hh));
    }
    __half* rp = P + (size_t)row * KP2;
    *(uint2*)(rp + c4)       = *(const uint2*)h;
    *(uint2*)(rp + DIM + c4) = *(const uint2*)L;
}

// 4 weights fused: W (fp32 [K,N]) -> B f16 [N][K] transposed, plane z
__global__ __launch_bounds__(256) void conv_w(
    const float* __restrict__ W0, const float* __restrict__ W1,
    const float* __restrict__ W2, const float* __restrict__ W3,
    __half* __restrict__ P)
{
    __shared__ float ws[32][33];
    const int k0 = blockIdx.x * 32;
    const int n0 = blockIdx.y * 32;
    const int z  = blockIdx.z;
    const float* W = (z == 0) ? W0 : (z == 1) ? W1 : (z == 2) ? W2 : W3;
    const int t  = threadIdx.x;

    {
        const int kr = t >> 3;
        const int c4 = (t & 7) * 4;
        float4 v = *(const float4*)(W + (size_t)(k0 + kr) * DIM + n0 + c4);
        ws[kr][c4 + 0] = v.x; ws[kr][c4 + 1] = v.y;
        ws[kr][c4 + 2] = v.z; ws[kr][c4 + 3] = v.w;
    }
    __syncthreads();

    const int nr = t >> 3;
    const int k4 = (t & 7) * 4;
    __align__(8) __half h[4];
    #pragma unroll
    for (int j = 0; j < 4; j++)
        h[j] = __float2half(ws[k4 + j][nr]);
    *(uint2*)(P + (size_t)z * DIM * DIM + (size_t)(n0 + nr) * DIM + k0 + k4)
        = *(const uint2*)h;
}

// ===========================================================================
// f16 GEMM: C = A @ W + bias.
// USE_LO=true : 2-product (A hi+lo), K-chunk 32, 3 stages — Q/K projections.
//               48 MMA / 16 LDSM per barrier (already at pipe ceiling).
// USE_LO=false: 1-product (A hi only), K-chunk 64, 3 stages — V proj, out-proj.
//               64 MMA / 24 LDSM per barrier (halved latency exposure).
// CTA 128x128, 8 warps (4m x 2n).
// mode = mode0 + blockIdx.z: 0 fp32 out; 1 Q f16 (hi,lo) scaled; 2 K; 3 V.
// ===========================================================================
#define GEMM_SMEM_LO (3 * 3 * 128 * 80)    // 92160
#define GEMM_SMEM_HI (3 * 2 * 128 * 144)   // 110592

template <bool USE_LO>
__global__ __launch_bounds__(256, 2) void gemm_mma(
    const __half* __restrict__ Ap, const __half* __restrict__ Bp,
    const float* __restrict__ bs0, const float* __restrict__ bs1,
    const float* __restrict__ bs2, float* __restrict__ C,
    __half* __restrict__ Qh, __half* __restrict__ Ql,
    __half* __restrict__ Kh, __half* __restrict__ Vh, int mode0)
{
    extern __shared__ __align__(128) char smem[];
    const uint32_t sb = smem_u32(smem);
    constexpr int CHUNK   = USE_LO ? 32 : 64;      // k per stage
    constexpr int SROWT   = USE_LO ? 80 : 144;     // bytes per k-row (+16 pad)
    constexpr int TILE_B2 = 128 * SROWT;
    constexpr int NTILES  = USE_LO ? 3 : 2;        // Ahi,(Alo),B
    constexpr int NSTG    = 3;
    constexpr int STAGE_B = NTILES * TILE_B2;
    constexpr int NCH     = DIM / CHUNK;           // 32 or 16
    constexpr int C16     = CHUNK / 8;             // 16B chunks per row
    constexpr int NU      = NTILES * 128 * C16 / 256;
    constexpr int NKI     = CHUNK / 16;

    const int tid  = threadIdx.x;
    const int lane = tid & 31;
    const int wid  = tid >> 5;
    const int wm   = (wid >> 1) * 32;
    const int wn   = (wid & 1) * 64;
    const int nt   = blockIdx.x;
    const int mt   = blockIdx.y;
    const int z    = blockIdx.z;
    const int mode = mode0 + z;
    const float* bias = (mode <= 1) ? bs0 : (mode == 2) ? bs1 : bs2;

    const __half* ag = Ap + (size_t)(mt * 128) * KP2;
    const __half* bg = Bp + (size_t)z * DIM * DIM + (size_t)(nt * 128) * DIM;

    auto issue = [&](int kc, int slot) {
        const uint32_t st = sb + slot * STAGE_B;
        #pragma unroll
        for (int u = 0; u < NU; u++) {
            const int id  = tid + u * 256;
            const int t3  = id / (128 * C16);
            const int rem = id % (128 * C16);
            const int r   = rem / C16;
            const int c   = rem % C16;
            const uint32_t dst = st + t3 * TILE_B2 + r * SROWT + c * 16;
            const __half* src = (t3 == NTILES - 1)
                ? bg + (size_t)r * DIM + kc * CHUNK + c * 8
                : ag + (size_t)r * KP2 + t3 * DIM + kc * CHUNK + c * 8;
            CP_ASYNC16(dst, src);
        }
        CP_COMMIT();
    };

    float acc[2][8][4];
    #pragma unroll
    for (int mi = 0; mi < 2; mi++)
        #pragma unroll
        for (int nj = 0; nj < 8; nj++)
            #pragma unroll
            for (int r = 0; r < 4; r++) acc[mi][nj][r] = 0.f;

    const uint32_t a_row = wm + (lane & 15);
    const uint32_t a_cc  = (lane >> 4) * 16;
    const uint32_t b_row = wn + ((lane >> 4) << 3) + (lane & 7);
    const uint32_t b_cc  = ((lane >> 3) & 1) * 16;

    issue(0, 0); issue(1, 1);

    for (int kc = 0; kc < NCH; kc++) {
        const int slot = kc % NSTG;
        CP_WAIT1();
        __syncthreads();
        if (kc + 2 < NCH) issue(kc + 2, (kc + 2) % NSTG);
        else CP_COMMIT();

        const uint32_t Ah = sb + slot * STAGE_B;
        const uint32_t Al = Ah + TILE_B2;
        const uint32_t Bs = Ah + (NTILES - 1) * TILE_B2;

        #pragma unroll
        for (int ki = 0; ki < NKI; ki++) {
            uint32_t ah[2][4], al[2][4], b[4][4];
            #pragma unroll
            for (int mi = 0; mi < 2; mi++) {
                LDSM_X4(ah[mi], Ah + (a_row + mi * 16) * SROWT + ki * 32 + a_cc);
                if (USE_LO)
                    LDSM_X4(al[mi], Al + (a_row + mi * 16) * SROWT + ki * 32 + a_cc);
            }
            #pragma unroll
            for (int ni = 0; ni < 4; ni++)
                LDSM_X4(b[ni], Bs + (b_row + ni * 16) * SROWT + ki * 32 + b_cc);
            #pragma unroll
            for (int mi = 0; mi < 2; mi++)
                #pragma unroll
                for (int nj = 0; nj < 8; nj++) {
                    const uint32_t b0 = b[nj >> 1][(nj & 1) * 2];
                    const uint32_t b1 = b[nj >> 1][(nj & 1) * 2 + 1];
                    MMA16816H(acc[mi][nj], ah[mi], b0, b1);
                    if (USE_LO)
                        MMA16816H(acc[mi][nj], al[mi], b0, b1);
                }
        }
    }

    const int g   = lane >> 2;
    const int tig = lane & 3;
    #pragma unroll
    for (int nj = 0; nj < 8; nj++) {
        const int col = nt * 128 + wn + nj * 8 + tig * 2;
        const float2 bv = *(const float2*)(bias + col);
        #pragma unroll
        for (int mi = 0; mi < 2; mi++) {
            const int m0 = mt * 128 + wm + mi * 16 + g;
            float2 d0 = {acc[mi][nj][0] + bv.x, acc[mi][nj][1] + bv.y};
            float2 d1 = {acc[mi][nj][2] + bv.x, acc[mi][nj][3] + bv.y};
            const size_t i0 = (size_t)m0 * DIM + col;
            const size_t i1 = (size_t)(m0 + 8) * DIM + col;
            if (mode == 0) {
                *(float2*)(C + i0) = d0;
                *(float2*)(C + i1) = d1;
            } else if (mode == 2) {
                *(__half2*)(Kh + i0) = __floats2half2_rn(d0.x, d0.y);
                *(__half2*)(Kh + i1) = __floats2half2_rn(d1.x, d1.y);
            } else if (mode == 3) {
                *(__half2*)(Vh + i0) = __floats2half2_rn(d0.x, d0.y);
                *(__half2*)(Vh + i1) = __floats2half2_rn(d1.x, d1.y);
            } else {
                d0.x *= QSCALE; d0.y *= QSCALE;
                d1.x *= QSCALE; d1.y *= QSCALE;
                __half2 h0 = __floats2half2_rn(d0.x, d0.y);
                __half2 h1 = __floats2half2_rn(d1.x, d1.y);
                *(__half2*)(Qh + i0) = h0;
                *(__half2*)(Qh + i1) = h1;
                *(__half2*)(Ql + i0) = __floats2half2_rn(
                    d0.x - __half2float(__low2half(h0)),
                    d0.y - __half2float(__high2half(h0)));
                *(__half2*)(Ql + i1) = __floats2half2_rn(
                    d1.x - __half2float(__low2half(h1)),
                    d1.y - __half2float(__high2half(h1)));
            }
        }
    }
}

// ===========================================================================
// HMMA flash attention. S = [Qhi|Qlo] . Kh  (2 f16 products); base-2 softmax
// with f32 ex2 (R12 known-good); P f16; O += P V; row-sums via ones-column
// MMA. 2-stage cp.async pipeline. Q frags reloaded from smem per k-chunk.
// Epilogue: o/l as f16 written to A-pack hi plane (out-proj is 1-product).
// ===========================================================================
#define ASROW 144
#define SMTILE (64 * ASROW)          // 9216
#define SMS0   (2 * SMTILE)          // Q hi/lo
#define SMSTAGE (2 * SMTILE)         // Kh, V
#define ATTN_SMEM (SMS0 + 2 * SMSTAGE)   // 55296
#define ONE2 0x3C003C00u

__global__ __launch_bounds__(128, 4) void attn_mma(
    const __half* __restrict__ Qhi, const __half* __restrict__ Qlo,
    const __half* __restrict__ Khp, const __half* __restrict__ Vhp,
    __half* __restrict__ Apack)
{
    extern __shared__ __align__(128) char smem[];
    const uint32_t sb = smem_u32(smem);
    const int tid = threadIdx.x, lane = tid & 31, w = tid >> 5;
    const int qt = blockIdx.x, h = blockIdx.y, b = blockIdx.z;
    const size_t hbase = (size_t)b * SEQ * DIM + (size_t)h * HD;

    // ---- Q hi/lo tiles (group with stage 0) ----
    #pragma unroll
    for (int u = 0; u < 8; u++) {
        const int id = tid + u * 128;
        const int t2 = id >> 9;
        const int r  = (id >> 3) & 63;
        const int c  = id & 7;
        const uint32_t dst = sb + t2 * SMTILE + r * ASROW + c * 16;
        const __half* src =
            (t2 ? Qlo : Qhi) + hbase + (size_t)(qt * 64 + r) * DIM + c * 8;
        CP_ASYNC16(dst, src);
    }
    auto issue_kv = [&](int st, int buf) {
        #pragma unroll
        for (int u = 0; u < 8; u++) {
            const int id = tid + u * 128;
            const int t2 = id >> 9;       // 0 Kh, 1 V
            const int r  = (id >> 3) & 63;
            const int c  = id & 7;
            const uint32_t dst = sb + SMS0 + buf * SMSTAGE + t2 * SMTILE
                               + r * ASROW + c * 16;
            const size_t off = hbase + (size_t)(st * 64 + r) * DIM + c * 8;
            const __half* src = t2 ? (Vhp + off) : (Khp + off);
            CP_ASYNC16(dst, src);
        }
    };
    issue_kv(0, 0); CP_COMMIT();
    issue_kv(1, 1); CP_COMMIT();
    CP_WAIT1();
    __syncthreads();

    // ---- lane-invariant addresses ----
    const uint32_t a_row = w * 16 + (lane & 15);
    const uint32_t a_cc  = (lane >> 4) * 16;
    const uint32_t qbase = sb + a_row * ASROW + a_cc;

    const uint32_t b_row = ((lane >> 4) << 3) + (lane & 7);
    const uint32_t b_cc  = ((lane >> 3) & 1) * 16;
    const uint32_t v_row = (((lane >> 3) & 1) << 3) + (lane & 7);
    const uint32_t v_cc  = (lane >> 4) * 16;

    float m0 = -1e30f, m1 = -1e30f;
    float Of[8][4], Lf[4] = {0.f, 0.f, 0.f, 0.f};
    #pragma unroll
    for (int nt = 0; nt < 8; nt++)
        #pragma unroll
        for (int r = 0; r < 4; r++) Of[nt][r] = 0.f;

    for (int st = 0; st < SEQ / 64; st++) {
        const uint32_t kb = sb + SMS0 + (st & 1) * SMSTAGE;

        // ---- S = Q K^T (2 f16 products; Q frags reloaded per k-chunk) ----
        float S[8][4];
        #pragma unroll
        for (int nt = 0; nt < 8; nt++)
            #pragma unroll
            for (int r = 0; r < 4; r++) S[nt][r] = 0.f;

        #pragma unroll
        for (int kc = 0; kc < 4; kc++) {
            uint32_t qhf[4], qlf[4];
            LDSM_X4(qhf, qbase + kc * 32);
            LDSM_X4(qlf, qbase + SMTILE + kc * 32);
            #pragma unroll
            for (int ng = 0; ng < 4; ng++) {
                uint32_t bh[4];
                LDSM_X4(bh, kb + (ng * 16 + b_row) * ASROW + kc * 32 + b_cc);
                MMA16816H(S[2 * ng],     qhf, bh[0], bh[1]);
                MMA16816H(S[2 * ng],     qlf, bh[0], bh[1]);
                MMA16816H(S[2 * ng + 1], qhf, bh[2], bh[3]);
                MMA16816H(S[2 * ng + 1], qlf, bh[2], bh[3]);
            }
        }

        // ---- online softmax (base 2) ----
        float mloc0 = -1e30f, mloc1 = -1e30f;
        #pragma unroll
        for (int nt = 0; nt < 8; nt++) {
            mloc0 = fmaxf(mloc0, fmaxf(S[nt][0], S[nt][1]));
            mloc1 = fmaxf(mloc1, fmaxf(S[nt][2], S[nt][3]));
        }
        mloc0 = fmaxf(mloc0, __shfl_xor_sync(0xffffffffu, mloc0, 1));
        mloc0 = fmaxf(mloc0, __shfl_xor_sync(0xffffffffu, mloc0, 2));
        mloc1 = fmaxf(mloc1, __shfl_xor_sync(0xffffffffu, mloc1, 1));
        mloc1 = fmaxf(mloc1, __shfl_xor_sync(0xffffffffu, mloc1, 2));
        const float mn0 = fmaxf(m0, mloc0), mn1 = fmaxf(m1, mloc1);
        float c0, c1;
        EX2F(c0, m0 - mn0); EX2F(c1, m1 - mn1);
        m0 = mn0; m1 = mn1;
        #pragma unroll
        for (int nt = 0; nt < 8; nt++) {
            Of[nt][0] *= c0; Of[nt][1] *= c0;
            Of[nt][2] *= c1; Of[nt][3] *= c1;
        }
        Lf[0] *= c0; Lf[1] *= c0; Lf[2] *= c1; Lf[3] *= c1;

        uint32_t pa[4][4];
        #pragma unroll
        for (int nt = 0; nt < 8; nt++) {
            float p0, p1, p2, p3;
            EX2F(p0, S[nt][0] - mn0); EX2F(p1, S[nt][1] - mn0);
            EX2F(p2, S[nt][2] - mn1); EX2F(p3, S[nt][3] - mn1);
            uint32_t g0, g8;
            PACK_F16X2(g0, p1, p0);
            PACK_F16X2(g8, p3, p2);
            pa[nt >> 1][(nt & 1) * 2 + 0] = g0;
            pa[nt >> 1][(nt & 1) * 2 + 1] = g8;
        }

        // ---- O += P V ; l += P.1 ----
        #pragma unroll
        for (int kc = 0; kc < 4; kc++) {
            MMA16816H(Lf, pa[kc], ONE2, ONE2);
            #pragma unroll
            for (int hg = 0; hg < 4; hg++) {
                uint32_t bv[4];
                LDSM_X4_T(bv, kb + SMTILE + (kc * 16 + v_row) * ASROW
                              + hg * 32 + v_cc);
                MMA16816H(Of[2 * hg],     pa[kc], bv[0], bv[1]);
                MMA16816H(Of[2 * hg + 1], pa[kc], bv[2], bv[3]);
            }
        }

        __syncthreads();
        if (st + 2 < SEQ / 64) issue_kv(st + 2, st & 1);
        CP_COMMIT();
        CP_WAIT1();
        __syncthreads();
    }

    // ---- finalize: o/l as f16 into A-pack hi plane (1-product out-proj) ----
    const float i0 = 1.f / Lf[0], i1 = 1.f / Lf[2];
    const int g = lane >> 2, tg = lane & 3;
    const size_t r0 = (size_t)b * SEQ + (size_t)qt * 64 + w * 16 + g;
    __half* rp0 = Apack + r0 * KP2;
    __half* rp1 = Apack + (r0 + 8) * KP2;
    #pragma unroll
    for (int nt = 0; nt < 8; nt++) {
        const int col = h * 64 + nt * 8 + tg * 2;
        *(__half2*)(rp0 + col) = __floats2half2_rn(Of[nt][0] * i0, Of[nt][1] * i0);
        *(__half2*)(rp1 + col) = __floats2half2_rn(Of[nt][2] * i1, Of[nt][3] * i1);
    }
}

// ===========================================================================
// launch
// ===========================================================================
extern "C" void kernel_launch(void* const* d_in, const int* in_sizes, int n_in,
                              void* d_out, int out_size)
{
    const float* x  = (const float*)d_in[0];
    const float* Wq = (const float*)d_in[1];
    const float* bq = (const float*)d_in[2];
    const float* Wk = (const float*)d_in[3];
    const float* bk = (const float*)d_in[4];
    const float* Wv = (const float*)d_in[5];
    const float* bv = (const float*)d_in[6];
    const float* Wo = (const float*)d_in[7];
    const float* bo = (const float*)d_in[8];
    float* out = (float*)d_out;

    __half *ap, *bp, *qhi, *qlo, *kh, *vh;
    cudaGetSymbolAddress((void**)&ap,  g_apack);
    cudaGetSymbolAddress((void**)&bp,  g_bpack);
    cudaGetSymbolAddress((void**)&qhi, g_qhi);
    cudaGetSymbolAddress((void**)&qlo, g_qlo);
    cudaGetSymbolAddress((void**)&kh,  g_kh);
    cudaGetSymbolAddress((void**)&vh,  g_vh);

    cudaFuncSetAttribute(gemm_mma<true>,
                         cudaFuncAttributeMaxDynamicSharedMemorySize, GEMM_SMEM_LO);
    cudaFuncSetAttribute(gemm_mma<false>,
                         cudaFuncAttributeMaxDynamicSharedMemorySize, GEMM_SMEM_HI);
    cudaFuncSetAttribute(attn_mma,
                         cudaFuncAttributeMaxDynamicSharedMemorySize, ATTN_SMEM);

    // fused weight conversion (4 planes)
    conv_w<<<dim3(32, 32, 4), 256>>>(Wq, Wk, Wv, Wo, bp);

    // x -> f16 hi/lo
    conv_a<<<ROWS, 256>>>(x, ap);

    // Q/K projections: 2-product (z selects plane / bias / epilogue mode 1,2)
    gemm_mma<true><<<dim3(8, 32, 2), 256, GEMM_SMEM_LO>>>(
        ap, bp, bq, bk, nullptr, nullptr, qhi, qlo, kh, nullptr, 1);

    // V projection: 1-product, K-chunk 64 (mode 3)
    gemm_mma<false><<<dim3(8, 32, 1), 256, GEMM_SMEM_HI>>>(
        ap, bp + 2 * (size_t)DIM * DIM, bv, bv, bv,
        nullptr, nullptr, nullptr, nullptr, vh, 3);

    // HMMA flash attention; epilogue writes f16 ctx into A-pack hi plane
    attn_mma<<<dim3(SEQ / 64, NHEADS, BATCH), 128, ATTN_SMEM>>>(
        qhi, qlo, kh, vh, ap);

    // output projection: 1-product, K-chunk 64 (mode 0, fp32 out)
    gemm_mma<false><<<dim3(8, 32, 1), 256, GEMM_SMEM_HI>>>(
        ap, bp + 3 * (size_t)DIM * DIM, bo, bo, bo,
        out, nullptr, nullptr, nullptr, nullptr, 0);
}

// round 16
// speedup vs baseline: 1.2163x; 1.1891x over previous
#include <cuda_runtime.h>
#include <cuda_bf16.h>
#include <cuda_fp16.h>
#include <cstdint>

#define DIM 1024
#define NHEADS 16
#define HD 64
#define BATCH 2
#define SEQ 2048
#define ROWS (BATCH*SEQ)   // 4096
#define KP2 2048           // f16 split A: [hi | lo]

// Q pre-scale: 1/sqrt(64) * log2(e)  (softmax done in base-2 domain)
#define QSCALE 0.1803368801111204f

// ---------------- scratch (device globals; no allocation allowed) ----------
__device__ __align__(16) __half g_qh [ROWS * DIM];
__device__ __align__(16) __half g_kh [ROWS * DIM];
__device__ __align__(16) __half g_vh [ROWS * DIM];
__device__ __align__(16) __half g_apack[ROWS * KP2];      // [Ah | Al]
__device__ __align__(16) __half g_bpack[4][DIM * DIM];    // W^T f16, 4 planes

// ===========================================================================
// PTX helpers
// ===========================================================================
__device__ __forceinline__ uint32_t smem_u32(const void* p) {
    uint32_t a;
    asm("{ .reg .u64 t; cvta.to.shared.u64 t, %1; cvt.u32.u64 %0, t; }"
        : "=r"(a) : "l"(p));
    return a;
}

#define CP_ASYNC16(dst, src) \
    asm volatile("cp.async.cg.shared.global [%0], [%1], 16;" \
                 :: "r"(dst), "l"(src) : "memory")
#define CP_COMMIT() asm volatile("cp.async.commit_group;" ::: "memory")
#define CP_WAIT1()  asm volatile("cp.async.wait_group 1;"  ::: "memory")

#define LDSM_X4(r, addr) \
    asm volatile("ldmatrix.sync.aligned.m8n8.x4.shared.b16 {%0,%1,%2,%3}, [%4];" \
        : "=r"((r)[0]), "=r"((r)[1]), "=r"((r)[2]), "=r"((r)[3]) : "r"(addr))

#define LDSM_X4_T(r, addr) \
    asm volatile("ldmatrix.sync.aligned.m8n8.x4.trans.shared.b16 {%0,%1,%2,%3}, [%4];" \
        : "=r"((r)[0]), "=r"((r)[1]), "=r"((r)[2]), "=r"((r)[3]) : "r"(addr))

#define MMA16816H(d, a, b0, b1) \
    asm volatile("mma.sync.aligned.m16n8k16.row.col.f32.f16.f16.f32 " \
        "{%0,%1,%2,%3}, {%4,%5,%6,%7}, {%8,%9}, {%0,%1,%2,%3};" \
        : "+f"((d)[0]), "+f"((d)[1]), "+f"((d)[2]), "+f"((d)[3]) \
        : "r"((a)[0]), "r"((a)[1]), "r"((a)[2]), "r"((a)[3]), "r"(b0), "r"(b1))

#define EX2F(d, x) asm("ex2.approx.ftz.f32 %0, %1;" : "=f"(d) : "f"(x))
// pack {hi,lo} f32 -> f16x2 (first source -> upper half)
#define PACK_F16X2(d, hi, lo) \
    asm("cvt.rn.f16x2.f32 %0, %1, %2;" : "=r"(d) : "f"(hi), "f"(lo))

// ===========================================================================
// conversion kernels
// ===========================================================================
// A (fp32 [4096,1024]) -> A' f16 [4096, 2048] = [hi | lo]
__global__ __launch_bounds__(256) void conv_a(
    const float* __restrict__ A, __half* __restrict__ P)
{
    const int row = blockIdx.x;
    const int c4  = threadIdx.x * 4;
    float4 v = *(const float4*)(A + (size_t)row * DIM + c4);
    float xs[4] = {v.x, v.y, v.z, v.w};
    __align__(8) __half h[4], L[4];
    #pragma unroll
    for (int j = 0; j < 4; j++) {
        __half hh = __float2half(xs[j]);
        h[j] = hh;
        L[j] = __float2half(xs[j] - __half2float(hh));
    }
    __half* rp = P + (size_t)row * KP2;
    *(uint2*)(rp + c4)       = *(const uint2*)h;
    *(uint2*)(rp + DIM + c4) = *(const uint2*)L;
}

// 4 weights fused: W (fp32 [K,N]) -> B f16 [N][K] transposed, plane z
__global__ __launch_bounds__(256) void conv_w(
    const float* __restrict__ W0, const float* __restrict__ W1,
    const float* __restrict__ W2, const float* __restrict__ W3,
    __half* __restrict__ P)
{
    __shared__ float ws[32][33];
    const int k0 = blockIdx.x * 32;
    const int n0 = blockIdx.y * 32;
    const int z  = blockIdx.z;
    const float* W = (z == 0) ? W0 : (z == 1) ? W1 : (z == 2) ? W2 : W3;
    const int t  = threadIdx.x;

    {
        const int kr = t >> 3;
        const int c4 = (t & 7) * 4;
        float4 v = *(const float4*)(W + (size_t)(k0 + kr) * DIM + n0 + c4);
        ws[kr][c4 + 0] = v.x; ws[kr][c4 + 1] = v.y;
        ws[kr][c4 + 2] = v.z; ws[kr][c4 + 3] = v.w;
    }
    __syncthreads();

    const int nr = t >> 3;
    const int k4 = (t & 7) * 4;
    __align__(8) __half h[4];
    #pragma unroll
    for (int j = 0; j < 4; j++)
        h[j] = __float2half(ws[k4 + j][nr]);
    *(uint2*)(P + (size_t)z * DIM * DIM + (size_t)(n0 + nr) * DIM + k0 + k4)
        = *(const uint2*)h;
}

// ===========================================================================
// f16 GEMM: C = A @ W + bias.
// USE_LO=true : 2-product (A hi+lo), K-chunk 32 — K projection only.
// USE_LO=false: 1-product (A hi),   K-chunk 64 — Q proj, V proj, out-proj.
// CTA 128x128, 8 warps (4m x 2n), 3-stage cp.async pipeline.
// mode0: 0 = out-proj (fp32 C); 2 = K; 9 = fused QV (z=0 -> Q f16 scaled,
// z=1 -> V f16; weight planes 0 and 2).
// ===========================================================================
#define GEMM_SMEM_LO (3 * 3 * 128 * 80)    // 92160
#define GEMM_SMEM_HI (3 * 2 * 128 * 144)   // 110592

template <bool USE_LO>
__global__ __launch_bounds__(256, 2) void gemm_mma(
    const __half* __restrict__ Ap, const __half* __restrict__ Bp,
    const float* __restrict__ bs0, const float* __restrict__ bs1,
    const float* __restrict__ bs2, float* __restrict__ C,
    __half* __restrict__ Qh, __half* __restrict__ Kh,
    __half* __restrict__ Vh, int mode0)
{
    extern __shared__ __align__(128) char smem[];
    const uint32_t sb = smem_u32(smem);
    constexpr int CHUNK   = USE_LO ? 32 : 64;      // k per stage
    constexpr int SROWT   = USE_LO ? 80 : 144;     // bytes per k-row (+16 pad)
    constexpr int TILE_B2 = 128 * SROWT;
    constexpr int NTILES  = USE_LO ? 3 : 2;        // Ahi,(Alo),B
    constexpr int NSTG    = 3;
    constexpr int STAGE_B = NTILES * TILE_B2;
    constexpr int NCH     = DIM / CHUNK;           // 32 or 16
    constexpr int C16     = CHUNK / 8;             // 16B chunks per row
    constexpr int NU      = NTILES * 128 * C16 / 256;
    constexpr int NKI     = CHUNK / 16;

    const int tid  = threadIdx.x;
    const int lane = tid & 31;
    const int wid  = tid >> 5;
    const int wm   = (wid >> 1) * 32;
    const int wn   = (wid & 1) * 64;
    const int nt   = blockIdx.x;
    const int mt   = blockIdx.y;
    const int z    = blockIdx.z;
    const int mode  = (mode0 == 9) ? (z ? 3 : 1) : mode0;
    const int plane = (mode0 == 9) ? 2 * z : 0;
    const float* bias = (mode <= 1) ? bs0 : (mode == 2) ? bs1 : bs2;

    const __half* ag = Ap + (size_t)(mt * 128) * KP2;
    const __half* bg = Bp + (size_t)plane * DIM * DIM + (size_t)(nt * 128) * DIM;

    auto issue = [&](int kc, int slot) {
        const uint32_t st = sb + slot * STAGE_B;
        #pragma unroll
        for (int u = 0; u < NU; u++) {
            const int id  = tid + u * 256;
            const int t3  = id / (128 * C16);
            const int rem = id % (128 * C16);
            const int r   = rem / C16;
            const int c   = rem % C16;
            const uint32_t dst = st + t3 * TILE_B2 + r * SROWT + c * 16;
            const __half* src = (t3 == NTILES - 1)
                ? bg + (size_t)r * DIM + kc * CHUNK + c * 8
                : ag + (size_t)r * KP2 + t3 * DIM + kc * CHUNK + c * 8;
            CP_ASYNC16(dst, src);
        }
        CP_COMMIT();
    };

    float acc[2][8][4];
    #pragma unroll
    for (int mi = 0; mi < 2; mi++)
        #pragma unroll
        for (int nj = 0; nj < 8; nj++)
            #pragma unroll
            for (int r = 0; r < 4; r++) acc[mi][nj][r] = 0.f;

    const uint32_t a_row = wm + (lane & 15);
    const uint32_t a_cc  = (lane >> 4) * 16;
    const uint32_t b_row = wn + ((lane >> 4) << 3) + (lane & 7);
    const uint32_t b_cc  = ((lane >> 3) & 1) * 16;

    issue(0, 0); issue(1, 1);

    for (int kc = 0; kc < NCH; kc++) {
        const int slot = kc % NSTG;
        CP_WAIT1();
        __syncthreads();
        if (kc + 2 < NCH) issue(kc + 2, (kc + 2) % NSTG);
        else CP_COMMIT();

        const uint32_t Ah = sb + slot * STAGE_B;
        const uint32_t Al = Ah + TILE_B2;
        const uint32_t Bs = Ah + (NTILES - 1) * TILE_B2;

        #pragma unroll
        for (int ki = 0; ki < NKI; ki++) {
            uint32_t ah[2][4], al[2][4], b[4][4];
            #pragma unroll
            for (int mi = 0; mi < 2; mi++) {
                LDSM_X4(ah[mi], Ah + (a_row + mi * 16) * SROWT + ki * 32 + a_cc);
                if (USE_LO)
                    LDSM_X4(al[mi], Al + (a_row + mi * 16) * SROWT + ki * 32 + a_cc);
            }
            #pragma unroll
            for (int ni = 0; ni < 4; ni++)
                LDSM_X4(b[ni], Bs + (b_row + ni * 16) * SROWT + ki * 32 + b_cc);
            #pragma unroll
            for (int mi = 0; mi < 2; mi++)
                #pragma unroll
                for (int nj = 0; nj < 8; nj++) {
                    const uint32_t b0 = b[nj >> 1][(nj & 1) * 2];
                    const uint32_t b1 = b[nj >> 1][(nj & 1) * 2 + 1];
                    MMA16816H(acc[mi][nj], ah[mi], b0, b1);
                    if (USE_LO)
                        MMA16816H(acc[mi][nj], al[mi], b0, b1);
                }
        }
    }

    const int g   = lane >> 2;
    const int tig = lane & 3;
    #pragma unroll
    for (int nj = 0; nj < 8; nj++) {
        const int col = nt * 128 + wn + nj * 8 + tig * 2;
        const float2 bv = *(const float2*)(bias + col);
        #pragma unroll
        for (int mi = 0; mi < 2; mi++) {
            const int m0 = mt * 128 + wm + mi * 16 + g;
            float2 d0 = {acc[mi][nj][0] + bv.x, acc[mi][nj][1] + bv.y};
            float2 d1 = {acc[mi][nj][2] + bv.x, acc[mi][nj][3] + bv.y};
            const size_t i0 = (size_t)m0 * DIM + col;
            const size_t i1 = (size_t)(m0 + 8) * DIM + col;
            if (mode == 0) {
                *(float2*)(C + i0) = d0;
                *(float2*)(C + i1) = d1;
            } else if (mode == 2) {
                *(__half2*)(Kh + i0) = __floats2half2_rn(d0.x, d0.y);
                *(__half2*)(Kh + i1) = __floats2half2_rn(d1.x, d1.y);
            } else if (mode == 3) {
                *(__half2*)(Vh + i0) = __floats2half2_rn(d0.x, d0.y);
                *(__half2*)(Vh + i1) = __floats2half2_rn(d1.x, d1.y);
            } else {   // mode 1: Q, pre-scaled, single f16 plane
                *(__half2*)(Qh + i0) =
                    __floats2half2_rn(d0.x * QSCALE, d0.y * QSCALE);
                *(__half2*)(Qh + i1) =
                    __floats2half2_rn(d1.x * QSCALE, d1.y * QSCALE);
            }
        }
    }
}

// ===========================================================================
// HMMA flash attention. S = Qh . Kh  (single f16 product); base-2 softmax;
// P f16; O += P V; row-sums via ones-column MMA. 2-stage cp.async pipeline.
// Epilogue: o/l as f16 written to A-pack hi plane (out-proj is 1-product).
// ===========================================================================
#define ASROW 144
#define SMTILE (64 * ASROW)          // 9216
#define SMS0   SMTILE                // single Q tile
#define SMSTAGE (2 * SMTILE)         // Kh, V
#define ATTN_SMEM (SMS0 + 2 * SMSTAGE)   // 46080
#define ONE2 0x3C003C00u

__global__ __launch_bounds__(128, 4) void attn_mma(
    const __half* __restrict__ Qhp, const __half* __restrict__ Khp,
    const __half* __restrict__ Vhp, __half* __restrict__ Apack)
{
    extern __shared__ __align__(128) char smem[];
    const uint32_t sb = smem_u32(smem);
    const int tid = threadIdx.x, lane = tid & 31, w = tid >> 5;
    const int qt = blockIdx.x, h = blockIdx.y, b = blockIdx.z;
    const size_t hbase = (size_t)b * SEQ * DIM + (size_t)h * HD;

    // ---- Q tile (group with stage 0) ----
    #pragma unroll
    for (int u = 0; u < 4; u++) {
        const int id = tid + u * 128;
        const int r  = id >> 3;
        const int c  = id & 7;
        const uint32_t dst = sb + r * ASROW + c * 16;
        CP_ASYNC16(dst, Qhp + hbase + (size_t)(qt * 64 + r) * DIM + c * 8);
    }
    auto issue_kv = [&](int st, int buf) {
        #pragma unroll
        for (int u = 0; u < 8; u++) {
            const int id = tid + u * 128;
            const int t2 = id >> 9;       // 0 Kh, 1 V
            const int r  = (id >> 3) & 63;
            const int c  = id & 7;
            const uint32_t dst = sb + SMS0 + buf * SMSTAGE + t2 * SMTILE
                               + r * ASROW + c * 16;
            const size_t off = hbase + (size_t)(st * 64 + r) * DIM + c * 8;
            const __half* src = t2 ? (Vhp + off) : (Khp + off);
            CP_ASYNC16(dst, src);
        }
    };
    issue_kv(0, 0); CP_COMMIT();
    issue_kv(1, 1); CP_COMMIT();
    CP_WAIT1();
    __syncthreads();

    // ---- lane-invariant addresses ----
    const uint32_t a_row = w * 16 + (lane & 15);
    const uint32_t a_cc  = (lane >> 4) * 16;
    const uint32_t qbase = sb + a_row * ASROW + a_cc;

    const uint32_t b_row = ((lane >> 4) << 3) + (lane & 7);
    const uint32_t b_cc  = ((lane >> 3) & 1) * 16;
    const uint32_t v_row = (((lane >> 3) & 1) << 3) + (lane & 7);
    const uint32_t v_cc  = (lane >> 4) * 16;

    float m0 = -1e30f, m1 = -1e30f;
    float Of[8][4], Lf[4] = {0.f, 0.f, 0.f, 0.f};
    #pragma unroll
    for (int nt = 0; nt < 8; nt++)
        #pragma unroll
        for (int r = 0; r < 4; r++) Of[nt][r] = 0.f;

    for (int st = 0; st < SEQ / 64; st++) {
        const uint32_t kb = sb + SMS0 + (st & 1) * SMSTAGE;

        // ---- S = Q K^T (single f16 product) ----
        float S[8][4];
        #pragma unroll
        for (int nt = 0; nt < 8; nt++)
            #pragma unroll
            for (int r = 0; r < 4; r++) S[nt][r] = 0.f;

        #pragma unroll
        for (int kc = 0; kc < 4; kc++) {
            uint32_t qhf[4];
            LDSM_X4(qhf, qbase + kc * 32);
            #pragma unroll
            for (int ng = 0; ng < 4; ng++) {
                uint32_t bh[4];
                LDSM_X4(bh, kb + (ng * 16 + b_row) * ASROW + kc * 32 + b_cc);
                MMA16816H(S[2 * ng],     qhf, bh[0], bh[1]);
                MMA16816H(S[2 * ng + 1], qhf, bh[2], bh[3]);
            }
        }

        // ---- online softmax (base 2) ----
        float mloc0 = -1e30f, mloc1 = -1e30f;
        #pragma unroll
        for (int nt = 0; nt < 8; nt++) {
            mloc0 = fmaxf(mloc0, fmaxf(S[nt][0], S[nt][1]));
            mloc1 = fmaxf(mloc1, fmaxf(S[nt][2], S[nt][3]));
        }
        mloc0 = fmaxf(mloc0, __shfl_xor_sync(0xffffffffu, mloc0, 1));
        mloc0 = fmaxf(mloc0, __shfl_xor_sync(0xffffffffu, mloc0, 2));
        mloc1 = fmaxf(mloc1, __shfl_xor_sync(0xffffffffu, mloc1, 1));
        mloc1 = fmaxf(mloc1, __shfl_xor_sync(0xffffffffu, mloc1, 2));
        const float mn0 = fmaxf(m0, mloc0), mn1 = fmaxf(m1, mloc1);
        float c0, c1;
        EX2F(c0, m0 - mn0); EX2F(c1, m1 - mn1);
        m0 = mn0; m1 = mn1;
        #pragma unroll
        for (int nt = 0; nt < 8; nt++) {
            Of[nt][0] *= c0; Of[nt][1] *= c0;
            Of[nt][2] *= c1; Of[nt][3] *= c1;
        }
        Lf[0] *= c0; Lf[1] *= c0; Lf[2] *= c1; Lf[3] *= c1;

        uint32_t pa[4][4];
        #pragma unroll
        for (int nt = 0; nt < 8; nt++) {
            float p0, p1, p2, p3;
            EX2F(p0, S[nt][0] - mn0); EX2F(p1, S[nt][1] - mn0);
            EX2F(p2, S[nt][2] - mn1); EX2F(p3, S[nt][3] - mn1);
            uint32_t g0, g8;
            PACK_F16X2(g0, p1, p0);
            PACK_F16X2(g8, p3, p2);
            pa[nt >> 1][(nt & 1) * 2 + 0] = g0;
            pa[nt >> 1][(nt & 1) * 2 + 1] = g8;
        }

        // ---- O += P V ; l += P.1 ----
        #pragma unroll
        for (int kc = 0; kc < 4; kc++) {
            MMA16816H(Lf, pa[kc], ONE2, ONE2);
            #pragma unroll
            for (int hg = 0; hg < 4; hg++) {
                uint32_t bv[4];
                LDSM_X4_T(bv, kb + SMTILE + (kc * 16 + v_row) * ASROW
                              + hg * 32 + v_cc);
                MMA16816H(Of[2 * hg],     pa[kc], bv[0], bv[1]);
                MMA16816H(Of[2 * hg + 1], pa[kc], bv[2], bv[3]);
            }
        }

        __syncthreads();
        if (st + 2 < SEQ / 64) issue_kv(st + 2, st & 1);
        CP_COMMIT();
        CP_WAIT1();
        __syncthreads();
    }

    // ---- finalize: o/l as f16 into A-pack hi plane (1-product out-proj) ----
    const float i0 = 1.f / Lf[0], i1 = 1.f / Lf[2];
    const int g = lane >> 2, tg = lane & 3;
    const size_t r0 = (size_t)b * SEQ + (size_t)qt * 64 + w * 16 + g;
    __half* rp0 = Apack + r0 * KP2;
    __half* rp1 = Apack + (r0 + 8) * KP2;
    #pragma unroll
    for (int nt = 0; nt < 8; nt++) {
        const int col = h * 64 + nt * 8 + tg * 2;
        *(__half2*)(rp0 + col) = __floats2half2_rn(Of[nt][0] * i0, Of[nt][1] * i0);
        *(__half2*)(rp1 + col) = __floats2half2_rn(Of[nt][2] * i1, Of[nt][3] * i1);
    }
}

// ===========================================================================
// launch
// ===========================================================================
extern "C" void kernel_launch(void* const* d_in, const int* in_sizes, int n_in,
                              void* d_out, int out_size)
{
    const float* x  = (const float*)d_in[0];
    const float* Wq = (const float*)d_in[1];
    const float* bq = (const float*)d_in[2];
    const float* Wk = (const float*)d_in[3];
    const float* bk = (const float*)d_in[4];
    const float* Wv = (const float*)d_in[5];
    const float* bv = (const float*)d_in[6];
    const float* Wo = (const float*)d_in[7];
    const float* bo = (const float*)d_in[8];
    float* out = (float*)d_out;

    __half *ap, *bp, *qh, *kh, *vh;
    cudaGetSymbolAddress((void**)&ap, g_apack);
    cudaGetSymbolAddress((void**)&bp, g_bpack);
    cudaGetSymbolAddress((void**)&qh, g_qh);
    cudaGetSymbolAddress((void**)&kh, g_kh);
    cudaGetSymbolAddress((void**)&vh, g_vh);

    cudaFuncSetAttribute(gemm_mma<true>,
                         cudaFuncAttributeMaxDynamicSharedMemorySize, GEMM_SMEM_LO);
    cudaFuncSetAttribute(gemm_mma<false>,
                         cudaFuncAttributeMaxDynamicSharedMemorySize, GEMM_SMEM_HI);
    cudaFuncSetAttribute(attn_mma,
                         cudaFuncAttributeMaxDynamicSharedMemorySize, ATTN_SMEM);

    // fused weight conversion (4 planes)
    conv_w<<<dim3(32, 32, 4), 256>>>(Wq, Wk, Wv, Wo, bp);

    // x -> f16 hi/lo
    conv_a<<<ROWS, 256>>>(x, ap);

    // K projection: 2-product (mode 2, plane 1 via pre-offset Bp)
    gemm_mma<true><<<dim3(8, 32, 1), 256, GEMM_SMEM_LO>>>(
        ap, bp + 1 * (size_t)DIM * DIM, bk, bk, bk,
        nullptr, nullptr, kh, nullptr, 2);

    // Q + V projections fused: 1-product (mode0=9: z=0 -> Q plane 0,
    // z=1 -> V plane 2)
    gemm_mma<false><<<dim3(8, 32, 2), 256, GEMM_SMEM_HI>>>(
        ap, bp, bq, bq, bv, nullptr, qh, nullptr, vh, 9);

    // HMMA flash attention; epilogue writes f16 ctx into A-pack hi plane
    attn_mma<<<dim3(SEQ / 64, NHEADS, BATCH), 128, ATTN_SMEM>>>(
        qh, kh, vh, ap);

    // output projection: 1-product (mode 0, fp32 out, plane 3 via offset)
    gemm_mma<false><<<dim3(8, 32, 1), 256, GEMM_SMEM_HI>>>(
        ap, bp + 3 * (size_t)DIM * DIM, bo, bo, bo,
        out, nullptr, nullptr, nullptr, 0);
}

// round 17
// speedup vs baseline: 1.3658x; 1.1229x over previous
#include <cuda_runtime.h>
#include <cuda_bf16.h>
#include <cuda_fp16.h>
#include <cstdint>

#define DIM 1024
#define NHEADS 16
#define HD 64
#define BATCH 2
#define SEQ 2048
#define ROWS (BATCH*SEQ)   // 4096

// Q pre-scale: 1/sqrt(64) * log2(e)  (softmax done in base-2 domain)
#define QSCALE 0.1803368801111204f

// ---------------- scratch (device globals; no allocation allowed) ----------
__device__ __align__(16) __half g_qh [ROWS * DIM];
__device__ __align__(16) __half g_kh [ROWS * DIM];
__device__ __align__(16) __half g_vh [ROWS * DIM];
__device__ __align__(16) __half g_xh [ROWS * DIM];        // x f16; later ctx
__device__ __align__(16) __half g_bpack[4][DIM * DIM];    // W^T f16, 4 planes

// ===========================================================================
// PTX helpers
// ===========================================================================
__device__ __forceinline__ uint32_t smem_u32(const void* p) {
    uint32_t a;
    asm("{ .reg .u64 t; cvta.to.shared.u64 t, %1; cvt.u32.u64 %0, t; }"
        : "=r"(a) : "l"(p));
    return a;
}

#define CP_ASYNC16(dst, src) \
    asm volatile("cp.async.cg.shared.global [%0], [%1], 16;" \
                 :: "r"(dst), "l"(src) : "memory")
#define CP_COMMIT() asm volatile("cp.async.commit_group;" ::: "memory")
#define CP_WAIT1()  asm volatile("cp.async.wait_group 1;"  ::: "memory")

#define LDSM_X4(r, addr) \
    asm volatile("ldmatrix.sync.aligned.m8n8.x4.shared.b16 {%0,%1,%2,%3}, [%4];" \
        : "=r"((r)[0]), "=r"((r)[1]), "=r"((r)[2]), "=r"((r)[3]) : "r"(addr))

#define LDSM_X4_T(r, addr) \
    asm volatile("ldmatrix.sync.aligned.m8n8.x4.trans.shared.b16 {%0,%1,%2,%3}, [%4];" \
        : "=r"((r)[0]), "=r"((r)[1]), "=r"((r)[2]), "=r"((r)[3]) : "r"(addr))

#define MMA16816H(d, a, b0, b1) \
    asm volatile("mma.sync.aligned.m16n8k16.row.col.f32.f16.f16.f32 " \
        "{%0,%1,%2,%3}, {%4,%5,%6,%7}, {%8,%9}, {%0,%1,%2,%3};" \
        : "+f"((d)[0]), "+f"((d)[1]), "+f"((d)[2]), "+f"((d)[3]) \
        : "r"((a)[0]), "r"((a)[1]), "r"((a)[2]), "r"((a)[3]), "r"(b0), "r"(b1))

#define EX2F(d, x) asm("ex2.approx.ftz.f32 %0, %1;" : "=f"(d) : "f"(x))
// pack {hi,lo} f32 -> f16x2 (first source -> upper half)
#define PACK_F16X2(d, hi, lo) \
    asm("cvt.rn.f16x2.f32 %0, %1, %2;" : "=r"(d) : "f"(hi), "f"(lo))

// ===========================================================================
// conversion kernels
// ===========================================================================
// x (fp32 [4096,1024]) -> f16 [4096,1024]
__global__ __launch_bounds__(256) void conv_a(
    const float* __restrict__ A, __half* __restrict__ P)
{
    const int row = blockIdx.x;
    const int c4  = threadIdx.x * 4;
    float4 v = *(const float4*)(A + (size_t)row * DIM + c4);
    __align__(8) __half h[4];
    h[0] = __float2half(v.x); h[1] = __float2half(v.y);
    h[2] = __float2half(v.z); h[3] = __float2half(v.w);
    *(uint2*)(P + (size_t)row * DIM + c4) = *(const uint2*)h;
}

// 4 weights fused: W (fp32 [K,N]) -> B f16 [N][K] transposed, plane z
__global__ __launch_bounds__(256) void conv_w(
    const float* __restrict__ W0, const float* __restrict__ W1,
    const float* __restrict__ W2, const float* __restrict__ W3,
    __half* __restrict__ P)
{
    __shared__ float ws[32][33];
    const int k0 = blockIdx.x * 32;
    const int n0 = blockIdx.y * 32;
    const int z  = blockIdx.z;
    const float* W = (z == 0) ? W0 : (z == 1) ? W1 : (z == 2) ? W2 : W3;
    const int t  = threadIdx.x;

    {
        const int kr = t >> 3;
        const int c4 = (t & 7) * 4;
        float4 v = *(const float4*)(W + (size_t)(k0 + kr) * DIM + n0 + c4);
        ws[kr][c4 + 0] = v.x; ws[kr][c4 + 1] = v.y;
        ws[kr][c4 + 2] = v.z; ws[kr][c4 + 3] = v.w;
    }
    __syncthreads();

    const int nr = t >> 3;
    const int k4 = (t & 7) * 4;
    __align__(8) __half h[4];
    #pragma unroll
    for (int j = 0; j < 4; j++)
        h[j] = __float2half(ws[k4 + j][nr]);
    *(uint2*)(P + (size_t)z * DIM * DIM + (size_t)(n0 + nr) * DIM + k0 + k4)
        = *(const uint2*)h;
}

// ===========================================================================
// f16 GEMM: C = A @ W + bias.  Single-product (A f16, W f16), K-chunk 64,
// 3-stage cp.async pipeline. CTA 128x128, 8 warps (4m x 2n).
// mode = mode0 + z (plane = z): 0 fp32 out; 1 Q f16 scaled; 2 K f16; 3 V f16.
// ===========================================================================
#define SROWT 144                   // bytes per 64-col f16 k-row (+16 pad)
#define TILE_B2 (128 * SROWT)       // 18432
#define STAGE_B (2 * TILE_B2)       // A, B
#define GEMM_SMEM (3 * STAGE_B)     // 110592
#define NCH 16                      // 1024 / 64

__global__ __launch_bounds__(256, 2) void gemm_mma(
    const __half* __restrict__ Ap, const __half* __restrict__ Bp,
    const float* __restrict__ bs0, const float* __restrict__ bs1,
    const float* __restrict__ bs2, float* __restrict__ C,
    __half* __restrict__ Qh, __half* __restrict__ Kh,
    __half* __restrict__ Vh, int mode0)
{
    extern __shared__ __align__(128) char smem[];
    const uint32_t sb = smem_u32(smem);

    const int tid  = threadIdx.x;
    const int lane = tid & 31;
    const int wid  = tid >> 5;
    const int wm   = (wid >> 1) * 32;
    const int wn   = (wid & 1) * 64;
    const int nt   = blockIdx.x;
    const int mt   = blockIdx.y;
    const int z    = blockIdx.z;
    const int mode = mode0 + z;
    const float* bias = (mode <= 1) ? bs0 : (mode == 2) ? bs1 : bs2;

    const __half* ag = Ap + (size_t)(mt * 128) * DIM;
    const __half* bg = Bp + (size_t)z * DIM * DIM + (size_t)(nt * 128) * DIM;

    // per stage: 2 tiles x 128 rows x 8 16B-chunks = 2048 cp.async / 256 thr
    auto issue = [&](int kc, int slot) {
        const uint32_t st = sb + slot * STAGE_B;
        #pragma unroll
        for (int u = 0; u < 8; u++) {
            const int id  = tid + u * 256;
            const int t2  = id >> 10;          // 0 A, 1 B
            const int r   = (id >> 3) & 127;
            const int c   = id & 7;
            const uint32_t dst = st + t2 * TILE_B2 + r * SROWT + c * 16;
            const __half* src = (t2 ? bg : ag) + (size_t)r * DIM
                              + kc * 64 + c * 8;
            CP_ASYNC16(dst, src);
        }
        CP_COMMIT();
    };

    float acc[2][8][4];
    #pragma unroll
    for (int mi = 0; mi < 2; mi++)
        #pragma unroll
        for (int nj = 0; nj < 8; nj++)
            #pragma unroll
            for (int r = 0; r < 4; r++) acc[mi][nj][r] = 0.f;

    const uint32_t a_row = wm + (lane & 15);
    const uint32_t a_cc  = (lane >> 4) * 16;
    const uint32_t b_row = wn + ((lane >> 4) << 3) + (lane & 7);
    const uint32_t b_cc  = ((lane >> 3) & 1) * 16;

    issue(0, 0); issue(1, 1);

    for (int kc = 0; kc < NCH; kc++) {
        const int slot = kc % 3;
        CP_WAIT1();
        __syncthreads();
        if (kc + 2 < NCH) issue(kc + 2, (kc + 2) % 3);
        else CP_COMMIT();

        const uint32_t As = sb + slot * STAGE_B;
        const uint32_t Bs = As + TILE_B2;

        #pragma unroll
        for (int ki = 0; ki < 4; ki++) {
            uint32_t a[2][4], b[4][4];
            #pragma unroll
            for (int mi = 0; mi < 2; mi++)
                LDSM_X4(a[mi], As + (a_row + mi * 16) * SROWT + ki * 32 + a_cc);
            #pragma unroll
            for (int ni = 0; ni < 4; ni++)
                LDSM_X4(b[ni], Bs + (b_row + ni * 16) * SROWT + ki * 32 + b_cc);
            #pragma unroll
            for (int mi = 0; mi < 2; mi++)
                #pragma unroll
                for (int nj = 0; nj < 8; nj++)
                    MMA16816H(acc[mi][nj], a[mi],
                              b[nj >> 1][(nj & 1) * 2], b[nj >> 1][(nj & 1) * 2 + 1]);
        }
    }

    const int g   = lane >> 2;
    const int tig = lane & 3;
    #pragma unroll
    for (int nj = 0; nj < 8; nj++) {
        const int col = nt * 128 + wn + nj * 8 + tig * 2;
        const float2 bv = *(const float2*)(bias + col);
        #pragma unroll
        for (int mi = 0; mi < 2; mi++) {
            const int m0 = mt * 128 + wm + mi * 16 + g;
            float2 d0 = {acc[mi][nj][0] + bv.x, acc[mi][nj][1] + bv.y};
            float2 d1 = {acc[mi][nj][2] + bv.x, acc[mi][nj][3] + bv.y};
            const size_t i0 = (size_t)m0 * DIM + col;
            const size_t i1 = (size_t)(m0 + 8) * DIM + col;
            if (mode == 0) {
                *(float2*)(C + i0) = d0;
                *(float2*)(C + i1) = d1;
            } else if (mode == 2) {
                *(__half2*)(Kh + i0) = __floats2half2_rn(d0.x, d0.y);
                *(__half2*)(Kh + i1) = __floats2half2_rn(d1.x, d1.y);
            } else if (mode == 3) {
                *(__half2*)(Vh + i0) = __floats2half2_rn(d0.x, d0.y);
                *(__half2*)(Vh + i1) = __floats2half2_rn(d1.x, d1.y);
            } else {   // mode 1: Q, pre-scaled
                *(__half2*)(Qh + i0) =
                    __floats2half2_rn(d0.x * QSCALE, d0.y * QSCALE);
                *(__half2*)(Qh + i1) =
                    __floats2half2_rn(d1.x * QSCALE, d1.y * QSCALE);
            }
        }
    }
}

// ===========================================================================
// HMMA flash attention. S = Qh . Kh  (single f16 product); base-2 softmax;
// P f16; O += P V; row-sums via ones-column MMA. 2-stage cp.async pipeline.
// Epilogue: o/l as f16 written straight into the ctx buffer (stride DIM).
// ===========================================================================
#define ASROW 144
#define SMTILE (64 * ASROW)          // 9216
#define SMS0   SMTILE                // single Q tile
#define SMSTAGE (2 * SMTILE)         // Kh, V
#define ATTN_SMEM (SMS0 + 2 * SMSTAGE)   // 46080
#define ONE2 0x3C003C00u

__global__ __launch_bounds__(128, 4) void attn_mma(
    const __half* __restrict__ Qhp, const __half* __restrict__ Khp,
    const __half* __restrict__ Vhp, __half* __restrict__ Ctx)
{
    extern __shared__ __align__(128) char smem[];
    const uint32_t sb = smem_u32(smem);
    const int tid = threadIdx.x, lane = tid & 31, w = tid >> 5;
    const int qt = blockIdx.x, h = blockIdx.y, b = blockIdx.z;
    const size_t hbase = (size_t)b * SEQ * DIM + (size_t)h * HD;

    // ---- Q tile (group with stage 0) ----
    #pragma unroll
    for (int u = 0; u < 4; u++) {
        const int id = tid + u * 128;
        const int r  = id >> 3;
        const int c  = id & 7;
        const uint32_t dst = sb + r * ASROW + c * 16;
        CP_ASYNC16(dst, Qhp + hbase + (size_t)(qt * 64 + r) * DIM + c * 8);
    }
    auto issue_kv = [&](int st, int buf) {
        #pragma unroll
        for (int u = 0; u < 8; u++) {
            const int id = tid + u * 128;
            const int t2 = id >> 9;       // 0 Kh, 1 V
            const int r  = (id >> 3) & 63;
            const int c  = id & 7;
            const uint32_t dst = sb + SMS0 + buf * SMSTAGE + t2 * SMTILE
                               + r * ASROW + c * 16;
            const size_t off = hbase + (size_t)(st * 64 + r) * DIM + c * 8;
            const __half* src = t2 ? (Vhp + off) : (Khp + off);
            CP_ASYNC16(dst, src);
        }
    };
    issue_kv(0, 0); CP_COMMIT();
    issue_kv(1, 1); CP_COMMIT();
    CP_WAIT1();
    __syncthreads();

    // ---- lane-invariant addresses ----
    const uint32_t a_row = w * 16 + (lane & 15);
    const uint32_t a_cc  = (lane >> 4) * 16;
    const uint32_t qbase = sb + a_row * ASROW + a_cc;

    const uint32_t b_row = ((lane >> 4) << 3) + (lane & 7);
    const uint32_t b_cc  = ((lane >> 3) & 1) * 16;
    const uint32_t v_row = (((lane >> 3) & 1) << 3) + (lane & 7);
    const uint32_t v_cc  = (lane >> 4) * 16;

    float m0 = -1e30f, m1 = -1e30f;
    float Of[8][4], Lf[4] = {0.f, 0.f, 0.f, 0.f};
    #pragma unroll
    for (int nt = 0; nt < 8; nt++)
        #pragma unroll
        for (int r = 0; r < 4; r++) Of[nt][r] = 0.f;

    for (int st = 0; st < SEQ / 64; st++) {
        const uint32_t kb = sb + SMS0 + (st & 1) * SMSTAGE;

        // ---- S = Q K^T (single f16 product) ----
        float S[8][4];
        #pragma unroll
        for (int nt = 0; nt < 8; nt++)
            #pragma unroll
            for (int r = 0; r < 4; r++) S[nt][r] = 0.f;

        #pragma unroll
        for (int kc = 0; kc < 4; kc++) {
            uint32_t qhf[4];
            LDSM_X4(qhf, qbase + kc * 32);
            #pragma unroll
            for (int ng = 0; ng < 4; ng++) {
                uint32_t bh[4];
                LDSM_X4(bh, kb + (ng * 16 + b_row) * ASROW + kc * 32 + b_cc);
                MMA16816H(S[2 * ng],     qhf, bh[0], bh[1]);
                MMA16816H(S[2 * ng + 1], qhf, bh[2], bh[3]);
            }
        }

        // ---- online softmax (base 2) ----
        float mloc0 = -1e30f, mloc1 = -1e30f;
        #pragma unroll
        for (int nt = 0; nt < 8; nt++) {
            mloc0 = fmaxf(mloc0, fmaxf(S[nt][0], S[nt][1]));
            mloc1 = fmaxf(mloc1, fmaxf(S[nt][2], S[nt][3]));
        }
        mloc0 = fmaxf(mloc0, __shfl_xor_sync(0xffffffffu, mloc0, 1));
        mloc0 = fmaxf(mloc0, __shfl_xor_sync(0xffffffffu, mloc0, 2));
        mloc1 = fmaxf(mloc1, __shfl_xor_sync(0xffffffffu, mloc1, 1));
        mloc1 = fmaxf(mloc1, __shfl_xor_sync(0xffffffffu, mloc1, 2));
        const float mn0 = fmaxf(m0, mloc0), mn1 = fmaxf(m1, mloc1);
        float c0, c1;
        EX2F(c0, m0 - mn0); EX2F(c1, m1 - mn1);
        m0 = mn0; m1 = mn1;
        #pragma unroll
        for (int nt = 0; nt < 8; nt++) {
            Of[nt][0] *= c0; Of[nt][1] *= c0;
            Of[nt][2] *= c1; Of[nt][3] *= c1;
        }
        Lf[0] *= c0; Lf[1] *= c0; Lf[2] *= c1; Lf[3] *= c1;

        uint32_t pa[4][4];
        #pragma unroll
        for (int nt = 0; nt < 8; nt++) {
            float p0, p1, p2, p3;
            EX2F(p0, S[nt][0] - mn0); EX2F(p1, S[nt][1] - mn0);
            EX2F(p2, S[nt][2] - mn1); EX2F(p3, S[nt][3] - mn1);
            uint32_t g0, g8;
            PACK_F16X2(g0, p1, p0);
            PACK_F16X2(g8, p3, p2);
            pa[nt >> 1][(nt & 1) * 2 + 0] = g0;
            pa[nt >> 1][(nt & 1) * 2 + 1] = g8;
        }

        // ---- O += P V ; l += P.1 ----
        #pragma unroll
        for (int kc = 0; kc < 4; kc++) {
            MMA16816H(Lf, pa[kc], ONE2, ONE2);
            #pragma unroll
            for (int hg = 0; hg < 4; hg++) {
                uint32_t bv[4];
                LDSM_X4_T(bv, kb + SMTILE + (kc * 16 + v_row) * ASROW
                              + hg * 32 + v_cc);
                MMA16816H(Of[2 * hg],     pa[kc], bv[0], bv[1]);
                MMA16816H(Of[2 * hg + 1], pa[kc], bv[2], bv[3]);
            }
        }

        __syncthreads();
        if (st + 2 < SEQ / 64) issue_kv(st + 2, st & 1);
        CP_COMMIT();
        CP_WAIT1();
        __syncthreads();
    }

    // ---- finalize: o/l as f16 into ctx buffer ----
    const float i0 = 1.f / Lf[0], i1 = 1.f / Lf[2];
    const int g = lane >> 2, tg = lane & 3;
    const size_t r0 = (size_t)b * SEQ + (size_t)qt * 64 + w * 16 + g;
    __half* rp0 = Ctx + r0 * DIM;
    __half* rp1 = Ctx + (r0 + 8) * DIM;
    #pragma unroll
    for (int nt = 0; nt < 8; nt++) {
        const int col = h * 64 + nt * 8 + tg * 2;
        *(__half2*)(rp0 + col) = __floats2half2_rn(Of[nt][0] * i0, Of[nt][1] * i0);
        *(__half2*)(rp1 + col) = __floats2half2_rn(Of[nt][2] * i1, Of[nt][3] * i1);
    }
}

// ===========================================================================
// launch
// ===========================================================================
extern "C" void kernel_launch(void* const* d_in, const int* in_sizes, int n_in,
                              void* d_out, int out_size)
{
    const float* x  = (const float*)d_in[0];
    const float* Wq = (const float*)d_in[1];
    const float* bq = (const float*)d_in[2];
    const float* Wk = (const float*)d_in[3];
    const float* bk = (const float*)d_in[4];
    const float* Wv = (const float*)d_in[5];
    const float* bv = (const float*)d_in[6];
    const float* Wo = (const float*)d_in[7];
    const float* bo = (const float*)d_in[8];
    float* out = (float*)d_out;

    __half *xh, *bp, *qh, *kh, *vh;
    cudaGetSymbolAddress((void**)&xh, g_xh);
    cudaGetSymbolAddress((void**)&bp, g_bpack);
    cudaGetSymbolAddress((void**)&qh, g_qh);
    cudaGetSymbolAddress((void**)&kh, g_kh);
    cudaGetSymbolAddress((void**)&vh, g_vh);

    cudaFuncSetAttribute(gemm_mma,
                         cudaFuncAttributeMaxDynamicSharedMemorySize, GEMM_SMEM);
    cudaFuncSetAttribute(attn_mma,
                         cudaFuncAttributeMaxDynamicSharedMemorySize, ATTN_SMEM);

    // fused weight conversion (4 planes)
    conv_w<<<dim3(32, 32, 4), 256>>>(Wq, Wk, Wv, Wo, bp);

    // x -> f16
    conv_a<<<ROWS, 256>>>(x, xh);

    // fused Q/K/V projections: z=0 Q (plane 0), z=1 K (plane 1), z=2 V (plane 2)
    gemm_mma<<<dim3(8, 32, 3), 256, GEMM_SMEM>>>(
        xh, bp, bq, bk, bv, nullptr, qh, kh, vh, 1);

    // HMMA flash attention; ctx written as f16 into g_xh (x is dead)
    attn_mma<<<dim3(SEQ / 64, NHEADS, BATCH), 128, ATTN_SMEM>>>(
        qh, kh, vh, xh);

    // output projection (plane 3 via pointer offset, fp32 out)
    gemm_mma<<<dim3(8, 32, 1), 256, GEMM_SMEM>>>(
        xh, bp + 3 * (size_t)DIM * DIM, bo, bo, bo,
        out, nullptr, nullptr, nullptr, 0);
}